// round 8
// baseline (speedup 1.0000x reference)
#include <cuda_runtime.h>
#include <cuda_fp16.h>
#include <math.h>
#include <stdint.h>

#define NN 50000
#define MP 50048          // NN padded to 128
#define DD 128
#define KK 32
#define TWO_D 256

// ---------------------------------------------------------------------------
// Global scratch
// ---------------------------------------------------------------------------
__device__ float g_wq[(size_t)NN * TWO_D];            // wq = [v|t] @ W.T
__device__ __half g_Whi[TWO_D * TWO_D];
__device__ __half g_Wlo[TWO_D * TWO_D];

// ---------------------------------------------------------------------------
// helpers
// ---------------------------------------------------------------------------
__device__ __forceinline__ uint32_t smem_u32(const void* p) {
    uint32_t a;
    asm("{ .reg .u64 t; cvta.to.shared.u64 t, %1; cvt.u32.u64 %0, t; }" : "=r"(a) : "l"(p));
    return a;
}
__device__ __forceinline__ void ldsm_x4(uint32_t* r, uint32_t addr) {
    asm volatile("ldmatrix.sync.aligned.m8n8.x4.shared.b16 {%0,%1,%2,%3}, [%4];"
                 : "=r"(r[0]), "=r"(r[1]), "=r"(r[2]), "=r"(r[3]) : "r"(addr));
}
__device__ __forceinline__ void mma16816h(float* d, const uint32_t* a, uint32_t b0, uint32_t b1) {
    asm volatile(
        "mma.sync.aligned.m16n8k16.row.col.f32.f16.f16.f32 "
        "{%0,%1,%2,%3}, {%4,%5,%6,%7}, {%8,%9}, {%0,%1,%2,%3};"
        : "+f"(d[0]), "+f"(d[1]), "+f"(d[2]), "+f"(d[3])
        : "r"(a[0]), "r"(a[1]), "r"(a[2]), "r"(a[3]), "r"(b0), "r"(b1));
}
__device__ __forceinline__ void cp16(uint32_t saddr, const void* gaddr) {
    asm volatile("cp.async.cg.shared.global [%0], [%1], 16;" :: "r"(saddr), "l"(gaddr));
}
__device__ __forceinline__ void cp_commit() {
    asm volatile("cp.async.commit_group;" ::: "memory");
}

// ---------------------------------------------------------------------------
// Kernel 0: W -> fp16 hi/lo split (once; W is tiny: 256x256)
// ---------------------------------------------------------------------------
__global__ __launch_bounds__(256) void w_split(const float* __restrict__ W) {
    int i = blockIdx.x * blockDim.x + threadIdx.x;    // 0..16383, 4 elems each
    float4 x = *(const float4*)(W + (size_t)i * 4);
    __half2 h01 = __floats2half2_rn(x.x, x.y);
    __half2 h23 = __floats2half2_rn(x.z, x.w);
    float l0 = x.x - __half2float(__low2half(h01));
    float l1 = x.y - __half2float(__high2half(h01));
    float l2 = x.z - __half2float(__low2half(h23));
    float l3 = x.w - __half2float(__high2half(h23));
    __half2 g01 = __floats2half2_rn(l0, l1);
    __half2 g23 = __floats2half2_rn(l2, l3);
    *(uint2*)(g_Whi + (size_t)i * 4) = make_uint2(*(uint32_t*)&h01, *(uint32_t*)&h23);
    *(uint2*)(g_Wlo + (size_t)i * 4) = make_uint2(*(uint32_t*)&g01, *(uint32_t*)&g23);
}

// ---------------------------------------------------------------------------
// Kernel 1: fused GEMM  g_wq[m][j] = sum_k A[m][k]*W[j][k], A=[v_fea|t_emb].
// BM=128, BN=64, 256 thr (8 warps 4x2). W hi/lo slab (64 rows x 256 k fp16)
// resident in smem for the whole CTA. Inner loop: A fp32 LDG -> fp16 cvt ->
// smem (double buffer), 2 accumulating HMMA passes (A*Whi + A*Wlo).
// ---------------------------------------------------------------------------
#define ROWW 528                      // 256 fp16 (512B) + 16B pad
#define WSLAB (64 * ROWW)             // 33792 per matrix
#define ROWB 80                       // 32 fp16 (64B) + 16B pad
#define ABUF (128 * ROWB)             // 10240
// smem: sWhi @0, sWlo @33792, sA[2] @67584/77824
#define SA_BASE 67584
#define GEMM_SMEM (SA_BASE + 2 * ABUF)   // 88064

__global__ void __launch_bounds__(256, 2) wq_gemm_fused(const float* __restrict__ v_fea,
                                                        const float* __restrict__ t_emb) {
    extern __shared__ char smem[];
    const uint32_t sbase = smem_u32(smem);
    const int tid = threadIdx.x;
    const int lane = tid & 31, w = tid >> 5;
    const int wm = w >> 1, wn = w & 1;
    const int m0 = blockIdx.x * 128;
    const int n0 = blockIdx.y * 64;

    // ---- W slab cp.async (one-time) ----
#pragma unroll
    for (int i = 0; i < 8; i++) {
        int idx = tid + i * 256;              // 0..2047
        int row = idx >> 5, seg = idx & 31;   // 64 rows x 32 16B-segs
        cp16(sbase + row * ROWW + seg * 16,
             g_Whi + (size_t)(n0 + row) * TWO_D + seg * 8);
        cp16(sbase + WSLAB + row * ROWW + seg * 16,
             g_Wlo + (size_t)(n0 + row) * TWO_D + seg * 8);
    }
    cp_commit();

    float acc[2][4][4];
#pragma unroll
    for (int i = 0; i < 2; i++)
#pragma unroll
        for (int j = 0; j < 4; j++)
#pragma unroll
            for (int q = 0; q < 4; q++) acc[i][j][q] = 0.f;

    // per-thread A staging geometry: row = tid>>1 (0..127), 16 cols
    const int arow = tid >> 1;
    const int acs = (tid & 1) * 16;
    const bool valid = (m0 + arow) < NN;
    const size_t abase_v = (size_t)(m0 + arow) * DD;

    float4 a[4];
    // ldg chunk helper (inline): chunk c covers cols (c<4 ? v : t)[(c&3)*32 ..]
#define LDG_CHUNK(c)                                                            \
    {                                                                           \
        const float* asrc = ((c) < 4) ? v_fea : t_emb;                          \
        int col0 = ((c) & 3) * 32 + acs;                                        \
        if (valid) {                                                            \
            a[0] = *(const float4*)(asrc + abase_v + col0);                     \
            a[1] = *(const float4*)(asrc + abase_v + col0 + 4);                 \
            a[2] = *(const float4*)(asrc + abase_v + col0 + 8);                 \
            a[3] = *(const float4*)(asrc + abase_v + col0 + 12);                \
        } else {                                                                \
            a[0] = a[1] = a[2] = a[3] = make_float4(0.f, 0.f, 0.f, 0.f);        \
        }                                                                       \
    }
#define CVT_CHUNK(buf)                                                          \
    {                                                                           \
        char* dst = smem + SA_BASE + (buf) * ABUF + arow * ROWB + acs * 2;      \
        _Pragma("unroll")                                                       \
        for (int i = 0; i < 4; i++) {                                           \
            __half2 h01 = __floats2half2_rn(a[i].x, a[i].y);                    \
            __half2 h23 = __floats2half2_rn(a[i].z, a[i].w);                    \
            *(uint2*)(dst + i * 8) = make_uint2(*(uint32_t*)&h01, *(uint32_t*)&h23); \
        }                                                                       \
    }

    // prologue
    LDG_CHUNK(0);
    asm volatile("cp.async.wait_group 0;" ::: "memory");
    __syncthreads();                       // W slab ready
    CVT_CHUNK(0);
    LDG_CHUNK(1);
    __syncthreads();                       // buf0 visible

    for (int c = 0; c < 8; c++) {
        const uint32_t aF = sbase + SA_BASE + (c & 1) * ABUF;
        const uint32_t wcolb = c * 64;     // byte offset of chunk within W row

        uint32_t afr[2][4], bfh[2][4], bfl[2][4];
        uint32_t afr2[2][4], bfh2[2][4], bfl2[2][4];
        // fragments ks=0
#pragma unroll
        for (int mi = 0; mi < 2; mi++) {
            int row = wm * 32 + mi * 16 + (lane & 15);
            uint32_t lo16 = ((lane >> 4) << 4);
            ldsm_x4(afr[mi], aF + row * ROWB + lo16);
            ldsm_x4(afr2[mi], aF + row * ROWB + 32 + lo16);
        }
#pragma unroll
        for (int nj2 = 0; nj2 < 2; nj2++) {
            int row = wn * 32 + nj2 * 16 + (lane & 15);
            uint32_t lo16 = ((lane >> 4) << 4);
            ldsm_x4(bfh[nj2], sbase + row * ROWW + wcolb + lo16);
            ldsm_x4(bfh2[nj2], sbase + row * ROWW + wcolb + 32 + lo16);
            ldsm_x4(bfl[nj2], sbase + WSLAB + row * ROWW + wcolb + lo16);
            ldsm_x4(bfl2[nj2], sbase + WSLAB + row * ROWW + wcolb + 32 + lo16);
        }

        if (c + 1 < 8) CVT_CHUNK((c + 1) & 1);
        if (c + 2 < 8) LDG_CHUNK(c + 2);

#pragma unroll
        for (int mi = 0; mi < 2; mi++)
#pragma unroll
            for (int nj = 0; nj < 4; nj++) {
                mma16816h(acc[mi][nj], afr[mi],
                          bfh[nj >> 1][nj & 1], bfh[nj >> 1][2 + (nj & 1)]);
                mma16816h(acc[mi][nj], afr[mi],
                          bfl[nj >> 1][nj & 1], bfl[nj >> 1][2 + (nj & 1)]);
                mma16816h(acc[mi][nj], afr2[mi],
                          bfh2[nj >> 1][nj & 1], bfh2[nj >> 1][2 + (nj & 1)]);
                mma16816h(acc[mi][nj], afr2[mi],
                          bfl2[nj >> 1][nj & 1], bfl2[nj >> 1][2 + (nj & 1)]);
            }
        __syncthreads();
    }
#undef LDG_CHUNK
#undef CVT_CHUNK

    // epilogue
    const int gid = lane >> 2, tig = lane & 3;
#pragma unroll
    for (int mi = 0; mi < 2; mi++) {
        int mrow = m0 + wm * 32 + mi * 16 + gid;
#pragma unroll
        for (int nj = 0; nj < 4; nj++) {
            int col = n0 + wn * 32 + nj * 8 + tig * 2;
            if (mrow < NN)
                *(float2*)(g_wq + (size_t)mrow * TWO_D + col) =
                    make_float2(acc[mi][nj][0], acc[mi][nj][1]);
            if (mrow + 8 < NN)
                *(float2*)(g_wq + (size_t)(mrow + 8) * TWO_D + col) =
                    make_float2(acc[mi][nj][2], acc[mi][nj][3]);
        }
    }
}

// ---------------------------------------------------------------------------
// Kernel 2: edge attention. wq rows staged in smem; __launch_bounds__(256,6)
// forces <=42 regs -> 48 warps/SM. NN = 6250*8 exactly (no guards).
// ---------------------------------------------------------------------------
__global__ void __launch_bounds__(256, 6) edge_attn(const float* __restrict__ v_fea,
                                                    const float* __restrict__ t_emb,
                                                    const int* __restrict__ ef,
                                                    float* __restrict__ out) {
    __shared__ float s_wq[8 * TWO_D];
    const int tid = threadIdx.x;
    const int node0 = blockIdx.x * 8;

    // cooperative copy of this block's 8 wq rows (contiguous 8*256 floats)
    {
        const float4* src = (const float4*)(g_wq + (size_t)node0 * TWO_D);
        float4* dst = (float4*)s_wq;
        dst[tid] = src[tid];
        dst[tid + 256] = src[tid + 256];
    }
    __syncthreads();

    const int w = tid >> 5, lane = tid & 31;
    const int node = node0 + w;
    const float* wqr = s_wq + w * TWO_D;

    const float4 wqa = *(const float4*)(wqr + lane * 4);
    const float4 wqb = *(const float4*)(wqr + DD + lane * 4);

    const int e_mine = ef[(size_t)node * KK + lane];

    float m1 = -INFINITY, s1 = 0.f;
    float m2 = -INFINITY, s2 = 0.f;
    float4 a1 = make_float4(0.f, 0.f, 0.f, 0.f);
    float4 a2 = make_float4(0.f, 0.f, 0.f, 0.f);

#pragma unroll 2
    for (int k = 0; k < KK; k += 2) {
        int e1 = __shfl_sync(0xffffffffu, e_mine, k);
        int e2 = __shfl_sync(0xffffffffu, e_mine, k + 1);
        const float4 v1 = *(const float4*)(v_fea + (size_t)e1 * DD + lane * 4);
        const float4 t1 = *(const float4*)(t_emb + (size_t)e1 * DD + lane * 4);
        const float4 v2 = *(const float4*)(v_fea + (size_t)e2 * DD + lane * 4);
        const float4 t2 = *(const float4*)(t_emb + (size_t)e2 * DD + lane * 4);

        float p1 = v1.x * wqa.x + v1.y * wqa.y + v1.z * wqa.z + v1.w * wqa.w
                 + t1.x * wqb.x + t1.y * wqb.y + t1.z * wqb.z + t1.w * wqb.w;
        float p2 = v2.x * wqa.x + v2.y * wqa.y + v2.z * wqa.z + v2.w * wqa.w
                 + t2.x * wqb.x + t2.y * wqb.y + t2.z * wqb.z + t2.w * wqb.w;
        p1 += __shfl_xor_sync(0xffffffffu, p1, 16);
        p2 += __shfl_xor_sync(0xffffffffu, p2, 16);
        p1 += __shfl_xor_sync(0xffffffffu, p1, 8);
        p2 += __shfl_xor_sync(0xffffffffu, p2, 8);
        p1 += __shfl_xor_sync(0xffffffffu, p1, 4);
        p2 += __shfl_xor_sync(0xffffffffu, p2, 4);
        p1 += __shfl_xor_sync(0xffffffffu, p1, 2);
        p2 += __shfl_xor_sync(0xffffffffu, p2, 2);
        p1 += __shfl_xor_sync(0xffffffffu, p1, 1);
        p2 += __shfl_xor_sync(0xffffffffu, p2, 1);

        float mn1 = fmaxf(m1, p1);
        float c1 = __expf(m1 - mn1);
        float w1 = __expf(p1 - mn1);
        s1 = s1 * c1 + w1;
        a1.x = a1.x * c1 + w1 * v1.x;
        a1.y = a1.y * c1 + w1 * v1.y;
        a1.z = a1.z * c1 + w1 * v1.z;
        a1.w = a1.w * c1 + w1 * v1.w;
        m1 = mn1;

        float mn2 = fmaxf(m2, p2);
        float c2 = __expf(m2 - mn2);
        float w2 = __expf(p2 - mn2);
        s2 = s2 * c2 + w2;
        a2.x = a2.x * c2 + w2 * v2.x;
        a2.y = a2.y * c2 + w2 * v2.y;
        a2.z = a2.z * c2 + w2 * v2.z;
        a2.w = a2.w * c2 + w2 * v2.w;
        m2 = mn2;
    }

    float mn = fmaxf(m1, m2);
    float c1 = __expf(m1 - mn), c2 = __expf(m2 - mn);
    float s = s1 * c1 + s2 * c2;
    const float inv = 1.f / s;
    float4 o;
    o.x = (a1.x * c1 + a2.x * c2) * inv;
    o.y = (a1.y * c1 + a2.y * c2) * inv;
    o.z = (a1.z * c1 + a2.z * c2) * inv;
    o.w = (a1.w * c1 + a2.w * c2) * inv;
    *(float4*)(out + (size_t)node * DD + lane * 4) = o;
}

// ---------------------------------------------------------------------------
extern "C" void kernel_launch(void* const* d_in, const int* in_sizes, int n_in,
                              void* d_out, int out_size) {
    const float* v_fea = (const float*)d_in[0];
    const float* t_emb = (const float*)d_in[1];
    const int* ef = (const int*)d_in[2];
    const float* W = (const float*)d_in[3];
    float* out = (float*)d_out;

    cudaFuncSetAttribute(wq_gemm_fused, cudaFuncAttributeMaxDynamicSharedMemorySize, GEMM_SMEM);

    w_split<<<TWO_D * TWO_D / 4 / 256, 256>>>(W);
    wq_gemm_fused<<<dim3(MP / 128, TWO_D / 64), 256, GEMM_SMEM>>>(v_fea, t_emb);
    edge_attn<<<NN / 8, 256>>>(v_fea, t_emb, ef, out);
}